// round 2
// baseline (speedup 1.0000x reference)
#include <cuda_runtime.h>
#include <math.h>
#include <stdint.h>

#define BB 4
#define MM 8192
#define NN 8192
#define NPAIRS (NN / 2)       // 4096 gt pairs per batch
#define BLOCKS 128            // BB*MM / 256
#define THREADS 256
#define BLOCKS_PER_BATCH 32   // MM / THREADS

// Scratch (no cudaMalloc allowed). Pairwise-SoA gt pack:
// pair j of batch b -> two float4 words:
//   word0 = {x0, x1, y0, y1}
//   word1 = {z0, z1, c0, c1}   with c = 0.5*(x^2+y^2+z^2)
__device__ float4 g_gtpack[BB * NPAIRS * 2];
__device__ float  g_partials[BLOCKS];

// ---- packed f32x2 helpers (sm_103a; ptxas never auto-fuses these) --------
__device__ __forceinline__ uint64_t pack2(float lo, float hi) {
    uint64_t r;
    asm("mov.b64 %0, {%1, %2};" : "=l"(r) : "f"(lo), "f"(hi));
    return r;
}
__device__ __forceinline__ uint64_t fma_f32x2(uint64_t a, uint64_t b, uint64_t c) {
    uint64_t d;
    asm("fma.rn.f32x2 %0, %1, %2, %3;" : "=l"(d) : "l"(a), "l"(b), "l"(c));
    return d;
}
__device__ __forceinline__ void unpack2(uint64_t v, float& lo, float& hi) {
    asm("mov.b64 {%0, %1}, %2;" : "=f"(lo), "=f"(hi) : "l"(v));
}

// ---------------------------------------------------------------------------
// Kernel 1: pack gt_colors [B, N, 3] -> pairwise-SoA float4 pairs.
// One thread per gt pair.
// ---------------------------------------------------------------------------
__global__ void prep_gt_kernel(const float* __restrict__ gt) {
    int j = blockIdx.x * blockDim.x + threadIdx.x;   // 0 .. BB*NPAIRS-1
    if (j < BB * NPAIRS) {
        int p0 = 2 * j;          // global point index of first of pair
        float x0 = gt[3 * p0 + 0], y0 = gt[3 * p0 + 1], z0 = gt[3 * p0 + 2];
        float x1 = gt[3 * p0 + 3], y1 = gt[3 * p0 + 4], z1 = gt[3 * p0 + 5];
        float c0 = 0.5f * (x0 * x0 + y0 * y0 + z0 * z0);
        float c1 = 0.5f * (x1 * x1 + y1 * y1 + z1 * z1);
        g_gtpack[2 * j + 0] = make_float4(x0, x1, y0, y1);
        g_gtpack[2 * j + 1] = make_float4(z0, z1, c0, c1);
    }
}

// ---------------------------------------------------------------------------
// Kernel 2: per pred point, min over all gt of t = |g|^2/2 - p.g  (packed x2)
// d2_min = |p|^2 + 2*t_min ; dist = sqrt(max(d2_min, 0))
// Each block: 256 pred points of one batch; batch's packed gt table in smem.
// ---------------------------------------------------------------------------
__global__ void __launch_bounds__(THREADS, 1)
min_dist_kernel(const float* __restrict__ pred) {
    extern __shared__ float4 sg[];   // NPAIRS*2 float4 = 128 KB

    const int b = blockIdx.x / BLOCKS_PER_BATCH;
    const int m = (blockIdx.x % BLOCKS_PER_BATCH) * THREADS + threadIdx.x;

    // Stage this batch's packed gt table into shared memory (coalesced f4).
    const float4* __restrict__ gbase = g_gtpack + b * NPAIRS * 2;
    #pragma unroll 8
    for (int i = threadIdx.x; i < NPAIRS * 2; i += THREADS) {
        sg[i] = gbase[i];
    }
    __syncthreads();

    // This thread's pred point (negated, lane-replicated into packed regs).
    const int gi = b * MM + m;
    const float px = pred[3 * gi + 0];
    const float py = pred[3 * gi + 1];
    const float pz = pred[3 * gi + 2];
    const uint64_t npx2 = pack2(-px, -px);
    const uint64_t npy2 = pack2(-py, -py);
    const uint64_t npz2 = pack2(-pz, -pz);

    // 8 independent partial-min accumulators (break FMNMX dep chain).
    float mn[8];
    #pragma unroll
    for (int j = 0; j < 8; j++) mn[j] = 3.402823466e38f;

    const uint64_t* __restrict__ sg64 = (const uint64_t*)sg;

    // Per pair: 2x LDS.128 (as 2x ulonglong2) + 3x FFMA2 + 2x FMNMX.
    #pragma unroll 2
    for (int n = 0; n < NPAIRS; n += 4) {
        #pragma unroll
        for (int j = 0; j < 4; j++) {
            // pair (n+j): sg64[4*(n+j)+0]={x0,x1} [+1]={y0,y1}
            //             [+2]={z0,z1}            [+3]={c0,c1}
            const uint64_t* p = sg64 + 4 * (n + j);
            uint64_t gx = p[0], gy = p[1], gz = p[2], gc = p[3];
            uint64_t t = fma_f32x2(npx2, gx, gc);
            t = fma_f32x2(npy2, gy, t);
            t = fma_f32x2(npz2, gz, t);
            float t0, t1;
            unpack2(t, t0, t1);
            mn[2 * j + 0] = fminf(mn[2 * j + 0], t0);
            mn[2 * j + 1] = fminf(mn[2 * j + 1], t1);
        }
    }

    float tmin = fminf(fminf(fminf(mn[0], mn[1]), fminf(mn[2], mn[3])),
                       fminf(fminf(mn[4], mn[5]), fminf(mn[6], mn[7])));

    float p2 = fmaf(px, px, fmaf(py, py, pz * pz));
    float d2 = fmaf(2.0f, tmin, p2);
    float dist = sqrtf(fmaxf(d2, 0.0f));

    // Block-level sum reduction (deterministic order).
    #pragma unroll
    for (int off = 16; off > 0; off >>= 1)
        dist += __shfl_down_sync(0xFFFFFFFFu, dist, off);

    __shared__ float warpsum[THREADS / 32];
    if ((threadIdx.x & 31) == 0) warpsum[threadIdx.x >> 5] = dist;
    __syncthreads();

    if (threadIdx.x < (THREADS / 32)) {
        float s = warpsum[threadIdx.x];
        #pragma unroll
        for (int off = (THREADS / 64); off > 0; off >>= 1)
            s += __shfl_down_sync(0xFFu, s, off);
        if (threadIdx.x == 0) g_partials[blockIdx.x] = s;
    }
}

// ---------------------------------------------------------------------------
// Kernel 3: sum 128 block partials -> mean -> out[0]
// ---------------------------------------------------------------------------
__global__ void finalize_kernel(float* __restrict__ out) {
    float s = g_partials[threadIdx.x];   // 128 threads, one partial each
    #pragma unroll
    for (int off = 16; off > 0; off >>= 1)
        s += __shfl_down_sync(0xFFFFFFFFu, s, off);

    __shared__ float ws[4];
    if ((threadIdx.x & 31) == 0) ws[threadIdx.x >> 5] = s;
    __syncthreads();

    if (threadIdx.x == 0) {
        float total = (ws[0] + ws[1]) + (ws[2] + ws[3]);
        out[0] = total * (1.0f / (float)(BB * MM));   // LOSS_WEIGHT = 1.0
    }
}

// ---------------------------------------------------------------------------
extern "C" void kernel_launch(void* const* d_in, const int* in_sizes, int n_in,
                              void* d_out, int out_size) {
    const float* pred = (const float*)d_in[0];   // [4, 8192, 3] f32
    const float* gt   = (const float*)d_in[1];   // [4, 8192, 3] f32
    float* out = (float*)d_out;

    (void)in_sizes; (void)n_in; (void)out_size;

    static bool attr_set = false;
    if (!attr_set) {
        cudaFuncSetAttribute(min_dist_kernel,
                             cudaFuncAttributeMaxDynamicSharedMemorySize,
                             NPAIRS * 2 * (int)sizeof(float4));   // 128 KB
        attr_set = true;
    }

    prep_gt_kernel<<<(BB * NPAIRS + 255) / 256, 256>>>(gt);
    min_dist_kernel<<<BLOCKS, THREADS, NPAIRS * 2 * sizeof(float4)>>>(pred);
    finalize_kernel<<<1, BLOCKS>>>(out);
}

// round 9
// speedup vs baseline: 1.5265x; 1.5265x over previous
#include <cuda_runtime.h>
#include <math.h>
#include <stdint.h>

#define BB 4
#define MM 8192
#define NN 8192
#define TOTP (BB * MM)            // 32768 pred points
#define THREADS 256
#define PPT 8                     // pred points per thread (4 packed f32x2 pairs)
#define PRED_PER_BLOCK (THREADS * PPT)          // 2048
#define PRED_BLOCKS (TOTP / PRED_PER_BLOCK)     // 16
#define CHUNK 256                 // gt points per chunk
#define NCHUNK (NN / CHUNK)       // 32
#define FBLOCKS (TOTP / THREADS)  // 128 finalize blocks

// Scratch (no cudaMalloc): per-(chunk, pred) partial min of t = |g|^2/2 - p.g
__device__ float g_part[NCHUNK * TOTP];   // 4 MB
__device__ float g_bsum[FBLOCKS];

// ---- packed f32x2 helpers (sm_103a; PTX-only, ptxas never auto-fuses) ----
__device__ __forceinline__ uint64_t pack2(float lo, float hi) {
    uint64_t r;
    asm("mov.b64 %0, {%1, %2};" : "=l"(r) : "f"(lo), "f"(hi));
    return r;
}
__device__ __forceinline__ uint64_t fma_f32x2(uint64_t a, uint64_t b, uint64_t c) {
    uint64_t d;
    asm("fma.rn.f32x2 %0, %1, %2, %3;" : "=l"(d) : "l"(a), "l"(b), "l"(c));
    return d;
}
__device__ __forceinline__ void unpack2(uint64_t v, float& lo, float& hi) {
    asm("mov.b64 {%0, %1}, %2;" : "=f"(lo), "=f"(hi) : "l"(v));
}

// ---------------------------------------------------------------------------
// Main kernel: block (pb, ch) evaluates 2048 pred points (of pb's batch)
// against gt chunk ch (256 points), writing per-pred partial t-min.
// gt chunk staged in smem lane-duplicated: {x,x},{y,y},{z,z},{c,c}.
// Per gt point per warp: 2 LDS.128 + 12 FFMA2 + 8 FMNMX covering 8 pred
// points x 32 lanes = 256 pair-evals.
// ---------------------------------------------------------------------------
__global__ void __launch_bounds__(THREADS)
chunk_min_kernel(const float* __restrict__ pred, const float* __restrict__ gt) {
    __shared__ float4 sg[CHUNK * 2];   // 8 KB -> ~4 blocks/SM resident

    const int tid = threadIdx.x;
    const int pb = blockIdx.x;         // 0..15 pred block
    const int ch = blockIdx.y;         // 0..31 gt chunk
    const int predbase = pb * PRED_PER_BLOCK;
    const int b = predbase / MM;       // batch
    const int gtbase = b * NN + ch * CHUNK;

    // Stage chunk: each of 256 threads packs one gt point (dup lanes).
    {
        const float* g = gt + 3 * (gtbase + tid);
        float x = g[0], y = g[1], z = g[2];
        float c = 0.5f * fmaf(x, x, fmaf(y, y, z * z));
        sg[2 * tid + 0] = make_float4(x, x, y, y);
        sg[2 * tid + 1] = make_float4(z, z, c, c);
    }

    // Load 8 pred points -> 4 packed (negated) coefficient sets.
    uint64_t npx2[4], npy2[4], npz2[4];
    #pragma unroll
    for (int q = 0; q < 4; q++) {
        int gi0 = predbase + (2 * q + 0) * THREADS + tid;
        int gi1 = predbase + (2 * q + 1) * THREADS + tid;
        float ax = pred[3 * gi0 + 0], ay = pred[3 * gi0 + 1], az = pred[3 * gi0 + 2];
        float bx = pred[3 * gi1 + 0], by = pred[3 * gi1 + 1], bz = pred[3 * gi1 + 2];
        npx2[q] = pack2(-ax, -bx);
        npy2[q] = pack2(-ay, -by);
        npz2[q] = pack2(-az, -bz);
    }

    float mn[8];
    #pragma unroll
    for (int k = 0; k < 8; k++) mn[k] = 3.402823466e38f;

    __syncthreads();

    const ulonglong2* __restrict__ s128 = (const ulonglong2*)sg;

    #pragma unroll 4
    for (int n = 0; n < CHUNK; n++) {
        ulonglong2 v0 = s128[2 * n + 0];   // {x,x},{y,y}
        ulonglong2 v1 = s128[2 * n + 1];   // {z,z},{c,c}
        #pragma unroll
        for (int q = 0; q < 4; q++) {
            uint64_t t = fma_f32x2(npx2[q], v0.x, v1.y);
            t = fma_f32x2(npy2[q], v0.y, t);
            t = fma_f32x2(npz2[q], v1.x, t);
            float t0, t1;
            unpack2(t, t0, t1);
            mn[2 * q + 0] = fminf(mn[2 * q + 0], t0);
            mn[2 * q + 1] = fminf(mn[2 * q + 1], t1);
        }
    }

    // Write partial mins: pred index for slot k is predbase + k*THREADS + tid.
    float* __restrict__ part = g_part + ch * TOTP + predbase + tid;
    #pragma unroll
    for (int k = 0; k < 8; k++) {
        part[k * THREADS] = mn[k];       // coalesced
    }
}

// ---------------------------------------------------------------------------
// Finalize A: per pred point, min over chunks -> dist; block-sum -> g_bsum.
// ---------------------------------------------------------------------------
__global__ void __launch_bounds__(THREADS)
reduce_kernel(const float* __restrict__ pred) {
    const int p = blockIdx.x * THREADS + threadIdx.x;   // 0..32767

    float tmin = 3.402823466e38f;
    #pragma unroll 8
    for (int c = 0; c < NCHUNK; c++) {
        tmin = fminf(tmin, g_part[c * TOTP + p]);
    }

    float px = pred[3 * p + 0], py = pred[3 * p + 1], pz = pred[3 * p + 2];
    float p2 = fmaf(px, px, fmaf(py, py, pz * pz));
    float d2 = fmaf(2.0f, tmin, p2);
    float dist = sqrtf(fmaxf(d2, 0.0f));

    #pragma unroll
    for (int off = 16; off > 0; off >>= 1)
        dist += __shfl_down_sync(0xFFFFFFFFu, dist, off);

    __shared__ float ws[THREADS / 32];
    if ((threadIdx.x & 31) == 0) ws[threadIdx.x >> 5] = dist;
    __syncthreads();

    if (threadIdx.x < (THREADS / 32)) {
        float s = ws[threadIdx.x];
        #pragma unroll
        for (int off = (THREADS / 64); off > 0; off >>= 1)
            s += __shfl_down_sync(0xFFu, s, off);
        if (threadIdx.x == 0) g_bsum[blockIdx.x] = s;
    }
}

// ---------------------------------------------------------------------------
// Finalize B: sum 128 block partials -> mean -> out[0]
// ---------------------------------------------------------------------------
__global__ void final_kernel(float* __restrict__ out) {
    float s = g_bsum[threadIdx.x];   // 128 threads
    #pragma unroll
    for (int off = 16; off > 0; off >>= 1)
        s += __shfl_down_sync(0xFFFFFFFFu, s, off);

    __shared__ float ws[4];
    if ((threadIdx.x & 31) == 0) ws[threadIdx.x >> 5] = s;
    __syncthreads();

    if (threadIdx.x == 0) {
        float total = (ws[0] + ws[1]) + (ws[2] + ws[3]);
        out[0] = total * (1.0f / (float)TOTP);   // LOSS_WEIGHT = 1.0
    }
}

// ---------------------------------------------------------------------------
extern "C" void kernel_launch(void* const* d_in, const int* in_sizes, int n_in,
                              void* d_out, int out_size) {
    const float* pred = (const float*)d_in[0];   // [4, 8192, 3] f32
    const float* gt   = (const float*)d_in[1];   // [4, 8192, 3] f32
    float* out = (float*)d_out;
    (void)in_sizes; (void)n_in; (void)out_size;

    dim3 grid(PRED_BLOCKS, NCHUNK);              // 16 x 32 = 512 blocks
    chunk_min_kernel<<<grid, THREADS>>>(pred, gt);
    reduce_kernel<<<FBLOCKS, THREADS>>>(pred);
    final_kernel<<<1, FBLOCKS>>>(out);
}